// round 7
// baseline (speedup 1.0000x reference)
#include <cuda_runtime.h>
#include <math.h>
#include <float.h>
#include <stdint.h>

// Problem constants (fixed by the reference)
#define B_IMG  32
#define D_DIM  256
#define HW_SZ  4096     // H*W = 64*64
#define K_CB   512
#define NCLS   10
#define NSHR   10

// Tiling
#define TP     256      // pixels per block
#define NTHR   256
#define NGRP   4        // code groups (tid>>6)
#define CPG    14       // usable codes per group (4*14 = 56 >= 51)
#define KTP    64       // cbT row stride: groups at 16-col boundaries

#define F32_INF __int_as_float(0x7f800000)

struct ClassRanges { int lo[NCLS]; int cnt[NCLS]; };

typedef unsigned long long ull;

// ---- packed f32x2 helpers (Blackwell): exact per-lane IEEE fp32 semantics --
__device__ __forceinline__ ull pack2(float x) {
    unsigned int b = __float_as_uint(x);
    ull r;
    asm("mov.b64 %0, {%1, %1};" : "=l"(r) : "r"(b));
    return r;
}
__device__ __forceinline__ void fma2(ull& d, ull a, ull b) {
    asm("fma.rn.f32x2 %0, %1, %2, %0;" : "+l"(d) : "l"(a), "l"(b));
}
__device__ __forceinline__ ull mul2(ull a, ull b) {
    ull r;
    asm("mul.rn.f32x2 %0, %1, %2;" : "=l"(r) : "l"(a), "l"(b));
    return r;
}
__device__ __forceinline__ void add2(ull& d, ull a) {
    asm("add.rn.f32x2 %0, %0, %1;" : "+l"(d) : "l"(a));
}
__device__ __forceinline__ float2 unpack2(ull v) {
    unsigned int lo, hi;
    asm("mov.b64 {%0, %1}, %2;" : "=r"(lo), "=r"(hi) : "l"(v));
    return make_float2(__uint_as_float(lo), __uint_as_float(hi));
}

// ----------------------------------------------------------------------------
// One block: image b, 256 contiguous pixels. Candidate codes = contiguous
// codebook slice [lo, lo+cnt), stored TRANSPOSED in smem: cbT[d][col],
// col = 16*(kk/14) + kk%14 (pad cols of each 16-col group are zero, p=+inf).
//
// Main loop is BARRIER-FREE: x comes straight from global (LDG.128, coalesced;
// cross-group reuse served by L1), codebook via broadcast LDS.128.
//
// Bit-exact replication of the reference fp32 arithmetic (validated round 2):
//   A   = in_sqr  : sequential ascending sum of fl(x_d*x_d)  (mul then add)
//   g_k = x . c_k : sequential ascending fused-FMA chain
//   d_k = fl( fl(A + p_k) - 2*g_k );  argmin, first-min tie-break
//   (storage col monotone in code index -> col-ascending scan == k-ascending)
// ----------------------------------------------------------------------------
__global__ void __launch_bounds__(NTHR, 2)
vq_kernel(const float* __restrict__ z, const float* __restrict__ cb,
          const int* __restrict__ labels, float* __restrict__ out,
          ClassRanges cr)
{
    extern __shared__ float smem[];
    float* cbT_s = smem;                      // [256 d][KTP]
    float* p_s   = cbT_s + D_DIM * KTP;       // [KTP] cb_sqr by col (+inf pads)
    float* A_s   = p_s + KTP;                 // [256] in_sqr per pixel
    float* rs    = A_s + 256;                 // [NGRP][256] best distance
    int*   ri    = (int*)(rs + NGRP * 256);   // [NGRP][256] storage cols
    int*   best  = (int*)(ri + NGRP * 256);   // [256]

    const int tid = threadIdx.x;
    const int tx  = tid & 31;
    const int wid = tid >> 5;                 // warp 0..7
    const int t64 = tid & 63;                 // lane within code group
    const int ty2 = tid >> 6;                 // code group 0..3
    const int px0 = t64 << 2;                 // 4 owned pixels
    const int b   = blockIdx.y;
    const int hw0 = blockIdx.x * TP;

    const int label = labels[b];
    const int lo    = cr.lo[label];
    const int cnt   = cr.cnt[label];          // 50 or 51

    // ---- init p_s to +inf, zero cbT (covers pad columns) ----
    if (tid < KTP) p_s[tid] = F32_INF;
    for (int i = tid; i < D_DIM * (KTP / 4); i += NTHR)
        *(float4*)&cbT_s[i << 2] = make_float4(0.f, 0.f, 0.f, 0.f);
    __syncthreads();

    // ---- build transposed codebook: cbT[d][col] = cb[lo+kk][d] ----
    for (int i = tid; i < 56 * (D_DIM / 4); i += NTHR) {
        const int kk  = i % 56;               // compact code index
        const int d4  = (i / 56) << 2;
        const int col = ((kk / CPG) << 4) + (kk % CPG);
        if (kk < cnt) {
            const float4 v = *(const float4*)(cb + (size_t)(lo + kk) * D_DIM + d4);
            cbT_s[(d4 + 0) * KTP + col] = v.x;
            cbT_s[(d4 + 1) * KTP + col] = v.y;
            cbT_s[(d4 + 2) * KTP + col] = v.z;
            cbT_s[(d4 + 3) * KTP + col] = v.w;
        }
    }

    // ---- cb_sqr per code from GLOBAL cb (coalesced), warp w -> codes 7w.. ----
    #pragma unroll
    for (int j = 0; j < 7; ++j) {
        const int kk = wid * 7 + j;           // 0..55
        if (kk < cnt) {
            const float* crow = cb + (size_t)(lo + kk) * D_DIM;
            float s = 0.0f;
            #pragma unroll
            for (int d = tx; d < D_DIM; d += 32) {
                const float v = __ldg(crow + d);
                s = __fadd_rn(s, __fmul_rn(v, v));
            }
            #pragma unroll
            for (int o = 16; o > 0; o >>= 1)
                s = __fadd_rn(s, __shfl_xor_sync(0xffffffffu, s, o));
            if (tx == 0) {
                const int col = ((kk / CPG) << 4) + (kk % CPG);
                p_s[col] = s;
            }
        }
    }
    __syncthreads();

    // ---- main loop: barrier-free, x via LDG.128, codes via LDS broadcast ----
    // Thread owns 4 pixels (px0..px0+3) x 14 codes (cols 16*ty2 .. +13).
    ull acc[7][4];
    #pragma unroll
    for (int j = 0; j < 7; ++j)
        #pragma unroll
        for (int p = 0; p < 4; ++p) acc[j][p] = 0ULL;
    ull asq[2];                               // in_sqr pairs (group 0 only)
    asq[0] = 0ULL; asq[1] = 0ULL;

    const float* xptr = z + (size_t)b * D_DIM * HW_SZ + hw0 + px0;
    const int colbase = ty2 << 4;
    const bool grp0 = (ty2 == 0);             // warp-uniform

    #pragma unroll 4
    for (int d = 0; d < D_DIM; ++d) {
        const float4 xv = __ldg((const float4*)(xptr + (size_t)d * HW_SZ));

        const float* crow = cbT_s + d * KTP + colbase;
        const float4 ca  = *(const float4*)(crow + 0);
        const float4 cbv = *(const float4*)(crow + 4);
        const float4 cc  = *(const float4*)(crow + 8);
        const float2 cd  = *(const float2*)(crow + 12);
        ull c[7];
        c[0] = *(const ull*)&ca.x;  c[1] = *(const ull*)&ca.z;
        c[2] = *(const ull*)&cbv.x; c[3] = *(const ull*)&cbv.z;
        c[4] = *(const ull*)&cc.x;  c[5] = *(const ull*)&cc.z;
        c[6] = *(const ull*)&cd.x;

        ull xd[4];
        xd[0] = pack2(xv.x); xd[1] = pack2(xv.y);
        xd[2] = pack2(xv.z); xd[3] = pack2(xv.w);

        if (grp0) {                            // in_sqr: per-pixel ascending-d
            const ull xy = *(const ull*)&xv.x; // pair (px0, px0+1)
            const ull zw = *(const ull*)&xv.z; // pair (px0+2, px0+3)
            add2(asq[0], mul2(xy, xy));
            add2(asq[1], mul2(zw, zw));
        }

        #pragma unroll
        for (int j = 0; j < 7; ++j)
            #pragma unroll
            for (int p = 0; p < 4; ++p) fma2(acc[j][p], xd[p], c[j]);
    }

    if (grp0) {
        *(float2*)&A_s[px0]     = unpack2(asq[0]);
        *(float2*)&A_s[px0 + 2] = unpack2(asq[1]);
    }
    __syncthreads();

    // ---- distances d = fl(fl(A + p) - 2g); per-thread first-min argmin ----
    #pragma unroll
    for (int p = 0; p < 4; ++p) {
        const float Av = A_s[px0 + p];
        float bd = F32_INF;
        int   bi = colbase;
        #pragma unroll
        for (int j = 0; j < 7; ++j) {
            const int c0i = colbase + (j << 1);
            const float2 g = unpack2(acc[j][p]);
            const float d0 = __fadd_rn(__fadd_rn(Av, p_s[c0i]), -(2.0f * g.x));
            const float d1 = __fadd_rn(__fadd_rn(Av, p_s[c0i + 1]), -(2.0f * g.y));
            if (d0 < bd) { bd = d0; bi = c0i; }      // strict <: lowest col wins
            if (d1 < bd) { bd = d1; bi = c0i + 1; }
        }
        rs[ty2 * 256 + px0 + p] = bd;
        ri[ty2 * 256 + px0 + p] = bi;
    }
    __syncthreads();

    {
        float bd = rs[tid];
        int   bi = ri[tid];
        #pragma unroll
        for (int t2 = 1; t2 < NGRP; ++t2) {
            const float s = rs[t2 * 256 + tid];
            if (s < bd) { bd = s; bi = ri[t2 * 256 + tid]; } // col ascends w/ grp
        }
        best[tid] = bi;
    }
    __syncthreads();

    // ---- epilogue: z_q_x = fl(x + fl(codes - x)), z_q_x_bar = codes ----
    const size_t obase = (size_t)b * D_DIM * HW_SZ + hw0;
    const float* zsrc  = z + obase;
    float* o0 = out + obase;
    float* o1 = out + (size_t)B_IMG * D_DIM * HW_SZ + obase;

    const int ep0 = (tid & 63) << 2;          // 4 pixels
    const int ed0 = tid >> 6;                 // d phase
    const int b0 = best[ep0 + 0];
    const int b1 = best[ep0 + 1];
    const int b2 = best[ep0 + 2];
    const int b3 = best[ep0 + 3];

    #pragma unroll 4
    for (int d = ed0; d < D_DIM; d += 4) {
        const size_t off = (size_t)d * HW_SZ + ep0;
        const float* crow = cbT_s + (size_t)d * KTP;
        const float4 xv = *(const float4*)(zsrc + off);
        float4 cv;
        cv.x = crow[b0]; cv.y = crow[b1]; cv.z = crow[b2]; cv.w = crow[b3];
        float4 q;
        q.x = __fadd_rn(xv.x, __fadd_rn(cv.x, -xv.x));
        q.y = __fadd_rn(xv.y, __fadd_rn(cv.y, -xv.y));
        q.z = __fadd_rn(xv.z, __fadd_rn(cv.z, -xv.z));
        q.w = __fadd_rn(xv.w, __fadd_rn(cv.w, -xv.w));
        *(float4*)(o0 + off) = q;
        *(float4*)(o1 + off) = cv;
    }
}

extern "C" void kernel_launch(void* const* d_in, const int* in_sizes, int n_in,
                              void* d_out, int out_size)
{
    const float* z      = (const float*)d_in[0];
    const float* cb     = (const float*)d_in[1];
    const int*   labels = (const int*)d_in[2];
    float*       out    = (float*)d_out;
    (void)in_sizes; (void)n_in; (void)out_size;

    // Class -> contiguous codebook range, replicating
    // round(linspace(-0.5, NCLS-0.51, K-NSHR)) exactly (double + half-even).
    ClassRanges cr;
    for (int c = 0; c < NCLS; ++c) { cr.lo[c] = 0; cr.cnt[c] = 0; }
    const double step = (((double)NCLS - 0.51) + 0.5) / (double)(K_CB - NSHR - 1);
    int prev = -1;
    for (int i = 0; i < K_CB - NSHR; ++i) {
        const double v = -0.5 + (double)i * step;
        int c = (int)nearbyint(v);
        if (c < 0) c = 0;
        if (c > NCLS - 1) c = NCLS - 1;
        if (c != prev) { cr.lo[c] = i; prev = c; }
        cr.cnt[c] += 1;
    }

    const size_t smem_bytes =
        (size_t)(D_DIM * KTP + KTP + 256 + NGRP * 256   // cbT, p, A, rs
                 + NGRP * 256 + 256) * sizeof(float);   // ri, best
    cudaFuncSetAttribute(vq_kernel,
                         cudaFuncAttributeMaxDynamicSharedMemorySize,
                         (int)smem_bytes);

    dim3 grid(HW_SZ / TP, B_IMG);
    vq_kernel<<<grid, NTHR, smem_bytes>>>(z, cb, labels, out, cr);
}